// round 12
// baseline (speedup 1.0000x reference)
#include <cuda_runtime.h>
#include <cuda_fp16.h>
#include <cstdint>

#define NB 2
#define NC 256
#define HW 2304   // 48*48
#define WD 48
#define NPIX (NB * HW)   // 4608

// ---------------- device scratch ----------------
__device__ float g_q[NB * NC * HW];
__device__ float g_k[NB * NC * HW];
__device__ float g_v[NB * NC * HW];
__device__ __half g_xt[NPIX * 256];        // x transposed, fp16
__device__ __half g_w[768 * 256];          // [wq;wk;wv] fp16

__device__ __forceinline__ uint32_t smem_u32(const void* p) {
    uint32_t a;
    asm("{ .reg .u64 t; cvta.to.shared.u64 t, %1; cvt.u32.u64 %0, t; }"
        : "=r"(a) : "l"(p));
    return a;
}
__device__ __forceinline__ uint32_t pack_h2(__half a, __half b) {
    return ((uint32_t)*(uint16_t*)&b << 16) | *(uint16_t*)&a;
}

// ---------------------------------------------------------------------------
// prep: z<2 -> transpose x to Xt[P][c] fp16 (float4 gmem loads);
//       z==2 -> weights fp16. grid (72, 8, 3), block 256.
// ---------------------------------------------------------------------------
__global__ __launch_bounds__(256) void prep_kernel(
    const float* __restrict__ x, const float* __restrict__ wq,
    const float* __restrict__ wk, const float* __restrict__ wv)
{
    int tid = threadIdx.x;
    if (blockIdx.z == 2) {
        int gid = (blockIdx.y * 72 + blockIdx.x) * 256 + tid;
        int lin = gid * 2;
        if (lin < 768 * 256) {
            int o = lin >> 8;
            int c = lin & 255;
            const float* src = (o < 256) ? (wq + o * 256)
                              : (o < 512) ? (wk + (o - 256) * 256)
                                          : (wv + (o - 512) * 256);
            float2 v = *(const float2*)(src + c);
            ((uint32_t*)g_w)[gid] = pack_h2(__float2half_rn(v.x),
                                            __float2half_rn(v.y));
        }
        return;
    }
    __shared__ float t[32][33];
    int p0 = blockIdx.x * 32;
    int c0 = blockIdx.y * 32;
    int b  = blockIdx.z;
    {
        int cl = tid >> 3;
        int p4 = (tid & 7) << 2;
        float4 v4 = *(const float4*)(x + (size_t)(b * 256 + c0 + cl) * HW
                                     + p0 + p4);
        t[cl][p4 + 0] = v4.x;
        t[cl][p4 + 1] = v4.y;
        t[cl][p4 + 2] = v4.z;
        t[cl][p4 + 3] = v4.w;
    }
    __syncthreads();
    int pl   = tid >> 3;
    int col8 = tid & 7;
    int c4   = col8 * 4;
    uint2 hi;
    hi.x = pack_h2(__float2half_rn(t[c4 + 0][pl]), __float2half_rn(t[c4 + 1][pl]));
    hi.y = pack_h2(__float2half_rn(t[c4 + 2][pl]), __float2half_rn(t[c4 + 3][pl]));
    size_t P = (size_t)b * HW + p0 + pl;
    *(uint2*)((char*)g_xt + P * 512 + c0 * 2 + col8 * 8) = hi;
}

// ---------------------------------------------------------------------------
// GEMM mma.sync m16n8k16 f16, single pass (R11-measured ~6.5us).
// Block 64oc x 128pix, K-tile 64, pitch 72 halves, 3 CTA/SM, grid (36,12).
// ---------------------------------------------------------------------------
#define A_TILE_B 9216
#define B_TILE_B 18432
#define GEMM_SMEM (A_TILE_B + B_TILE_B)

__device__ __forceinline__ void mma_f16(float* d, const uint32_t* a,
                                        const uint32_t* b) {
    asm volatile(
        "mma.sync.aligned.m16n8k16.row.col.f32.f16.f16.f32 "
        "{%0,%1,%2,%3}, {%4,%5,%6,%7}, {%8,%9}, {%0,%1,%2,%3};"
        : "+f"(d[0]), "+f"(d[1]), "+f"(d[2]), "+f"(d[3])
        : "r"(a[0]), "r"(a[1]), "r"(a[2]), "r"(a[3]), "r"(b[0]), "r"(b[1]));
}

__global__ __launch_bounds__(256, 3) void gemm_kernel() {
    extern __shared__ char sm[];
    uint32_t uS = smem_u32(sm);

    int tid = threadIdx.x;
    int l   = tid & 31;
    int wid = tid >> 5;
    int wm  = wid >> 2;
    int wn  = wid & 3;

    int N0 = blockIdx.x * 128;
    int M0 = blockIdx.y * 64;

    const char* aw = (const char*)g_w  + (size_t)M0 * 512;
    const char* bx = (const char*)g_xt + (size_t)N0 * 512;

    float acc[2][4][4];
    #pragma unroll
    for (int i = 0; i < 2; i++)
        #pragma unroll
        for (int j = 0; j < 4; j++)
            #pragma unroll
            for (int r = 0; r < 4; r++) acc[i][j][r] = 0.f;

    uint32_t aLane = (uint32_t)((wm * 32 + (l & 15)) * 144 + (l >> 4) * 16);
    uint32_t bLane = (uint32_t)((wn * 32 + ((l >> 4) & 1) * 8 + (l & 7)) * 144
                                + ((l >> 3) & 1) * 16);

    for (int kt = 0; kt < 4; kt++) {
        __syncthreads();
        #pragma unroll
        for (int it = 0; it < 6; it++) {
            int lin = it * 256 + tid;
            if (lin < 512) {
                int row = lin >> 3;
                int ch  = lin & 7;
                uint4 v = *(const uint4*)(aw + row * 512 + kt * 128 + ch * 16);
                *(uint4*)(sm + row * 144 + ch * 16) = v;
            } else {
                int rem = lin - 512;
                int row = rem >> 3;
                int ch  = rem & 7;
                uint4 v = *(const uint4*)(bx + row * 512 + kt * 128 + ch * 16);
                *(uint4*)(sm + A_TILE_B + row * 144 + ch * 16) = v;
            }
        }
        __syncthreads();

        uint32_t aBase = uS + aLane;
        uint32_t bBase = uS + A_TILE_B + bLane;
        #pragma unroll
        for (int ks = 0; ks < 4; ks++) {
            uint32_t af[2][4];
            uint32_t bf[4][2];
            #pragma unroll
            for (int i = 0; i < 2; i++) {
                uint32_t ad = aBase + i * (16 * 144) + ks * 32;
                asm volatile(
                    "ldmatrix.sync.aligned.m8n8.x4.shared.b16 "
                    "{%0,%1,%2,%3}, [%4];"
                    : "=r"(af[i][0]), "=r"(af[i][1]),
                      "=r"(af[i][2]), "=r"(af[i][3]) : "r"(ad));
            }
            #pragma unroll
            for (int jp = 0; jp < 2; jp++) {
                uint32_t bd = bBase + jp * (16 * 144) + ks * 32;
                asm volatile(
                    "ldmatrix.sync.aligned.m8n8.x4.shared.b16 "
                    "{%0,%1,%2,%3}, [%4];"
                    : "=r"(bf[2 * jp][0]), "=r"(bf[2 * jp][1]),
                      "=r"(bf[2 * jp + 1][0]), "=r"(bf[2 * jp + 1][1])
                    : "r"(bd));
            }
            #pragma unroll
            for (int i = 0; i < 2; i++)
                #pragma unroll
                for (int j = 0; j < 4; j++)
                    mma_f16(acc[i][j], af[i], bf[j]);
        }
    }

    int b  = N0 / HW;
    int pl = N0 - b * HW;
    float* obuf = (M0 < 256) ? g_q : (M0 < 512) ? g_k : g_v;
    int ol = M0 & 255;
    int g  = l >> 2;
    int tc = l & 3;
    float* base = obuf + (size_t)b * NC * HW;

    #pragma unroll
    for (int i = 0; i < 2; i++) {
        int oc0 = ol + wm * 32 + i * 16 + g;
        #pragma unroll
        for (int j = 0; j < 4; j++) {
            int pix = pl + wn * 32 + j * 8 + tc * 2;
            *(float2*)(base + (size_t)oc0 * HW + pix) =
                make_float2(acc[i][j][0], acc[i][j][1]);
            *(float2*)(base + (size_t)(oc0 + 8) * HW + pix) =
                make_float2(acc[i][j][2], acc[i][j][3]);
        }
    }
}

// ---------------------------------------------------------------------------
// Attention v5: 2 px/thread -> small live set (~46 regs), 576 threads,
// __launch_bounds__(576,2) -> 2 CTA/SM = 36 warps/SM (vs 27).
// 1024 blocks (plane x half). Window = 10 cols via 5x LDS.64 (w0 even).
// Per tap: FFMA + EX2 + FADD + FFMA, qb[2][7] table for both bias modes.
// ---------------------------------------------------------------------------
template <bool USEH>
__device__ __forceinline__ void attn_body(
    const float* __restrict__ ks,
    const float* __restrict__ qrow, float* __restrict__ orow,
    const float* bias, int r, int w0)
{
    const float LOG2E = 1.4426950408889634f;
    float2 q2 = *(const float2*)(qrow + w0);
    float ql[2] = {q2.x * LOG2E, q2.y * LOG2E};
    float qb[2][7];
    #pragma unroll
    for (int o = 0; o < 2; o++)
        #pragma unroll
        for (int j = 0; j < 7; j++) qb[o][j] = ql[o] * bias[j];

    float ssum[2] = {0.f, 0.f};
    float avec[2] = {0.f, 0.f};

    #pragma unroll
    for (int kh = 0; kh < 7; kh++) {
        const float* kr = &ks[(r + kh) * 56 + w0];
        float kvv[10], vvv[10];
        #pragma unroll
        for (int j = 0; j < 5; j++) {
            float2 a = *(const float2*)(kr + 2 * j);
            kvv[2 * j] = a.x; kvv[2 * j + 1] = a.y;
            float2 b = *(const float2*)(kr + 1680 + 2 * j);   // v tile offset
            vvv[2 * j] = b.x; vvv[2 * j + 1] = b.y;
        }
        #pragma unroll
        for (int kw = 0; kw < 7; kw++) {
            #pragma unroll
            for (int o = 0; o < 2; o++) {
                int idx = o + kw + 1;
                float qbb = USEH ? qb[o][kh] : qb[o][kw];
                float t = fmaf(ql[o], kvv[idx], qbb);
                float e;
                asm("ex2.approx.f32 %0, %1;" : "=f"(e) : "f"(t));
                ssum[o] += e;
                avec[o] = fmaf(e, vvv[idx], avec[o]);
            }
        }
    }
    float inv[2];
    #pragma unroll
    for (int o = 0; o < 2; o++)
        asm("rcp.approx.f32 %0, %1;" : "=f"(inv[o]) : "f"(ssum[o]));
    *(float2*)(orow + w0) = make_float2(avec[0] * inv[0], avec[1] * inv[1]);
}

__global__ __launch_bounds__(576, 2) void attn_kernel(
    const float* __restrict__ rel_h, const float* __restrict__ rel_w,
    float* __restrict__ out)
{
    __shared__ float kvbuf[2 * 30 * 56];   // k tile then v tile, 1680 floats each
    float* ks = kvbuf;
    float* vs = kvbuf + 1680;

    int plane = blockIdx.x >> 1;
    int half  = blockIdx.x & 1;
    int y0    = half * 24;
    int ybase = y0 - 3;
    int c = plane & 255;
    bool useH = (c < 128);

    const float* kp = g_k + (size_t)plane * HW;
    const float* vp = g_v + (size_t)plane * HW;
    const float* qp = g_q + (size_t)plane * HW;
    float*       op = out + (size_t)plane * HW;

    int tid = threadIdx.x;

    #pragma unroll
    for (int i = tid; i < 840; i += 576)
        ((float4*)kvbuf)[i] = make_float4(0.f, 0.f, 0.f, 0.f);
    __syncthreads();
    if (tid < 360) {
        int r  = tid / 12;
        int x4 = (tid - r * 12) << 2;
        int gy = ybase + r;
        if ((unsigned)gy < 48u) {
            *(float4*)(ks + r * 56 + x4 + 4) = *(const float4*)(kp + gy * WD + x4);
            *(float4*)(vs + r * 56 + x4 + 4) = *(const float4*)(vp + gy * WD + x4);
        }
    }
    const float* rb = useH ? (rel_h + c * 7) : (rel_w + (c - 128) * 7);
    float bias[7];
    #pragma unroll
    for (int j = 0; j < 7; j++) bias[j] = rb[j];
    __syncthreads();

    int r  = tid / 24;                   // 0..23 local row
    int w0 = (tid - r * 24) << 1;        // 0,2,..,46
    int gy = y0 + r;
    const float* qrow = qp + gy * WD;
    float*       orow = op + gy * WD;

    if (useH) attn_body<true >(ks, qrow, orow, bias, r, w0);
    else      attn_body<false>(ks, qrow, orow, bias, r, w0);
}

extern "C" void kernel_launch(void* const* d_in, const int* in_sizes, int n_in,
                              void* d_out, int out_size) {
    const float* x  = (const float*)d_in[0];
    const float* wq = (const float*)d_in[1];
    const float* wk = (const float*)d_in[2];
    const float* wv = (const float*)d_in[3];
    const float* rh = (const float*)d_in[4];
    const float* rw = (const float*)d_in[5];

    cudaFuncSetAttribute(gemm_kernel, cudaFuncAttributeMaxDynamicSharedMemorySize,
                         GEMM_SMEM);

    prep_kernel<<<dim3(72, 8, 3), 256>>>(x, wq, wk, wv);
    gemm_kernel<<<dim3(36, 12), 256, GEMM_SMEM>>>();
    attn_kernel<<<1024, 576>>>(rh, rw, (float*)d_out);
}

// round 13
// speedup vs baseline: 1.0492x; 1.0492x over previous
#include <cuda_runtime.h>
#include <cuda_fp16.h>
#include <cstdint>

#define NB 2
#define NC 256
#define HW 2304   // 48*48
#define WD 48
#define NPIX (NB * HW)   // 4608

// ---------------- device scratch ----------------
__device__ float g_q[NB * NC * HW];
__device__ float g_k[NB * NC * HW];
__device__ float g_v[NB * NC * HW];
__device__ __half g_xt[NPIX * 256];        // x transposed, fp16
__device__ __half g_w[768 * 256];          // [wq;wk;wv] fp16

__device__ __forceinline__ uint32_t smem_u32(const void* p) {
    uint32_t a;
    asm("{ .reg .u64 t; cvta.to.shared.u64 t, %1; cvt.u32.u64 %0, t; }"
        : "=r"(a) : "l"(p));
    return a;
}
__device__ __forceinline__ uint32_t pack_h2(__half a, __half b) {
    return ((uint32_t)*(uint16_t*)&b << 16) | *(uint16_t*)&a;
}

// ---------------------------------------------------------------------------
// prep v2 (ILP=4): z<2 -> transpose x to Xt[P][c] fp16, 4 subtiles/block
// (4 independent loads in flight per thread); z==2 -> weights fp16.
// grid (18, 8, 3), block 256.
// ---------------------------------------------------------------------------
__global__ __launch_bounds__(256) void prep_kernel(
    const float* __restrict__ x, const float* __restrict__ wq,
    const float* __restrict__ wk, const float* __restrict__ wv)
{
    int tid = threadIdx.x;
    if (blockIdx.z == 2) {
        int gid = (blockIdx.y * 18 + blockIdx.x) * 256 + tid;   // 0..36863
        for (int i = gid; i < 49152; i += 36864) {              // uint2 items
            int lin = i << 2;                                   // half index
            int o = lin >> 8;
            int c = lin & 255;
            const float* src = (o < 256) ? (wq + o * 256)
                              : (o < 512) ? (wk + (o - 256) * 256)
                                          : (wv + (o - 512) * 256);
            float4 v = *(const float4*)(src + c);
            uint2 r;
            r.x = pack_h2(__float2half_rn(v.x), __float2half_rn(v.y));
            r.y = pack_h2(__float2half_rn(v.z), __float2half_rn(v.w));
            *(uint2*)((char*)g_w + (size_t)lin * 2) = r;
        }
        return;
    }
    __shared__ float t[4][32][33];
    int p0 = blockIdx.x * 128;
    int c0 = blockIdx.y * 32;
    int b  = blockIdx.z;
    {
        // 4 independent coalesced load rounds (original R11 pattern x4)
        #pragma unroll
        for (int s = 0; s < 4; s++) {
            #pragma unroll
            for (int k = 0; k < 4; k++) {
                int idx = k * 256 + tid;
                int cl  = idx >> 5;
                int pl  = idx & 31;
                t[s][cl][pl] = x[(size_t)(b * 256 + c0 + cl) * HW
                                 + p0 + s * 32 + pl];
            }
        }
    }
    __syncthreads();
    int pl   = tid >> 3;
    int col8 = tid & 7;
    int c4   = col8 * 4;
    #pragma unroll
    for (int s = 0; s < 4; s++) {
        uint2 hi;
        hi.x = pack_h2(__float2half_rn(t[s][c4 + 0][pl]),
                       __float2half_rn(t[s][c4 + 1][pl]));
        hi.y = pack_h2(__float2half_rn(t[s][c4 + 2][pl]),
                       __float2half_rn(t[s][c4 + 3][pl]));
        size_t P = (size_t)b * HW + p0 + s * 32 + pl;
        *(uint2*)((char*)g_xt + P * 512 + c0 * 2 + col8 * 8) = hi;
    }
}

// ---------------------------------------------------------------------------
// GEMM mma.sync m16n8k16 f16, single pass (R11-measured ~6.5us, unchanged).
// Block 64oc x 128pix, K-tile 64, pitch 72 halves, 3 CTA/SM, grid (36,12).
// ---------------------------------------------------------------------------
#define A_TILE_B 9216
#define B_TILE_B 18432
#define GEMM_SMEM (A_TILE_B + B_TILE_B)

__device__ __forceinline__ void mma_f16(float* d, const uint32_t* a,
                                        const uint32_t* b) {
    asm volatile(
        "mma.sync.aligned.m16n8k16.row.col.f32.f16.f16.f32 "
        "{%0,%1,%2,%3}, {%4,%5,%6,%7}, {%8,%9}, {%0,%1,%2,%3};"
        : "+f"(d[0]), "+f"(d[1]), "+f"(d[2]), "+f"(d[3])
        : "r"(a[0]), "r"(a[1]), "r"(a[2]), "r"(a[3]), "r"(b[0]), "r"(b[1]));
}

__global__ __launch_bounds__(256, 3) void gemm_kernel() {
    extern __shared__ char sm[];
    uint32_t uS = smem_u32(sm);

    int tid = threadIdx.x;
    int l   = tid & 31;
    int wid = tid >> 5;
    int wm  = wid >> 2;
    int wn  = wid & 3;

    int N0 = blockIdx.x * 128;
    int M0 = blockIdx.y * 64;

    const char* aw = (const char*)g_w  + (size_t)M0 * 512;
    const char* bx = (const char*)g_xt + (size_t)N0 * 512;

    float acc[2][4][4];
    #pragma unroll
    for (int i = 0; i < 2; i++)
        #pragma unroll
        for (int j = 0; j < 4; j++)
            #pragma unroll
            for (int r = 0; r < 4; r++) acc[i][j][r] = 0.f;

    uint32_t aLane = (uint32_t)((wm * 32 + (l & 15)) * 144 + (l >> 4) * 16);
    uint32_t bLane = (uint32_t)((wn * 32 + ((l >> 4) & 1) * 8 + (l & 7)) * 144
                                + ((l >> 3) & 1) * 16);

    for (int kt = 0; kt < 4; kt++) {
        __syncthreads();
        #pragma unroll
        for (int it = 0; it < 6; it++) {
            int lin = it * 256 + tid;
            if (lin < 512) {
                int row = lin >> 3;
                int ch  = lin & 7;
                uint4 v = *(const uint4*)(aw + row * 512 + kt * 128 + ch * 16);
                *(uint4*)(sm + row * 144 + ch * 16) = v;
            } else {
                int rem = lin - 512;
                int row = rem >> 3;
                int ch  = rem & 7;
                uint4 v = *(const uint4*)(bx + row * 512 + kt * 128 + ch * 16);
                *(uint4*)(sm + A_TILE_B + row * 144 + ch * 16) = v;
            }
        }
        __syncthreads();

        uint32_t aBase = uS + aLane;
        uint32_t bBase = uS + A_TILE_B + bLane;
        #pragma unroll
        for (int ks = 0; ks < 4; ks++) {
            uint32_t af[2][4];
            uint32_t bf[4][2];
            #pragma unroll
            for (int i = 0; i < 2; i++) {
                uint32_t ad = aBase + i * (16 * 144) + ks * 32;
                asm volatile(
                    "ldmatrix.sync.aligned.m8n8.x4.shared.b16 "
                    "{%0,%1,%2,%3}, [%4];"
                    : "=r"(af[i][0]), "=r"(af[i][1]),
                      "=r"(af[i][2]), "=r"(af[i][3]) : "r"(ad));
            }
            #pragma unroll
            for (int jp = 0; jp < 2; jp++) {
                uint32_t bd = bBase + jp * (16 * 144) + ks * 32;
                asm volatile(
                    "ldmatrix.sync.aligned.m8n8.x4.shared.b16 "
                    "{%0,%1,%2,%3}, [%4];"
                    : "=r"(bf[2 * jp][0]), "=r"(bf[2 * jp][1]),
                      "=r"(bf[2 * jp + 1][0]), "=r"(bf[2 * jp + 1][1])
                    : "r"(bd));
            }
            #pragma unroll
            for (int i = 0; i < 2; i++)
                #pragma unroll
                for (int j = 0; j < 4; j++)
                    mma_f16(acc[i][j], af[i], bf[j]);
        }
    }

    int b  = N0 / HW;
    int pl = N0 - b * HW;
    float* obuf = (M0 < 256) ? g_q : (M0 < 512) ? g_k : g_v;
    int ol = M0 & 255;
    int g  = l >> 2;
    int tc = l & 3;
    float* base = obuf + (size_t)b * NC * HW;

    #pragma unroll
    for (int i = 0; i < 2; i++) {
        int oc0 = ol + wm * 32 + i * 16 + g;
        #pragma unroll
        for (int j = 0; j < 4; j++) {
            int pix = pl + wn * 32 + j * 8 + tc * 2;
            *(float2*)(base + (size_t)oc0 * HW + pix) =
                make_float2(acc[i][j][0], acc[i][j][1]);
            *(float2*)(base + (size_t)(oc0 + 8) * HW + pix) =
                make_float2(acc[i][j][2], acc[i][j][3]);
        }
    }
}

// ---------------------------------------------------------------------------
// Attention v3.1: compute identical to R11 (72 regs, 3 CTA/SM, 4 px/thread).
// Fill optimized: halo-only clear (disjoint from interior fill -> single
// barrier, no full-tile clear).
// ---------------------------------------------------------------------------
template <bool USEH>
__device__ __forceinline__ void attn_body(
    const float* __restrict__ ks, const float* __restrict__ vs,
    const float* __restrict__ qrow, float* __restrict__ orow,
    const float* bias, int r, int w0)
{
    const float LOG2E = 1.4426950408889634f;
    float4 q4 = *(const float4*)(qrow + w0);
    float ql[4] = {q4.x * LOG2E, q4.y * LOG2E, q4.z * LOG2E, q4.w * LOG2E};
    float qb[4][7];
    #pragma unroll
    for (int o = 0; o < 4; o++)
        #pragma unroll
        for (int j = 0; j < 7; j++) qb[o][j] = ql[o] * bias[j];

    float ssum[4] = {0.f, 0.f, 0.f, 0.f};
    float avec[4] = {0.f, 0.f, 0.f, 0.f};

    #pragma unroll
    for (int kh = 0; kh < 7; kh++) {
        const float* kr = &ks[(r + kh) * 56 + w0];
        const float* vr = &vs[(r + kh) * 56 + w0];
        float kvv[12], vvv[12];
        {
            float4 t0 = *(const float4*)(kr);
            float4 t1 = *(const float4*)(kr + 4);
            float4 t2 = *(const float4*)(kr + 8);
            kvv[0]=t0.x; kvv[1]=t0.y; kvv[2]=t0.z; kvv[3]=t0.w;
            kvv[4]=t1.x; kvv[5]=t1.y; kvv[6]=t1.z; kvv[7]=t1.w;
            kvv[8]=t2.x; kvv[9]=t2.y; kvv[10]=t2.z; kvv[11]=t2.w;
            float4 u0 = *(const float4*)(vr);
            float4 u1 = *(const float4*)(vr + 4);
            float4 u2 = *(const float4*)(vr + 8);
            vvv[0]=u0.x; vvv[1]=u0.y; vvv[2]=u0.z; vvv[3]=u0.w;
            vvv[4]=u1.x; vvv[5]=u1.y; vvv[6]=u1.z; vvv[7]=u1.w;
            vvv[8]=u2.x; vvv[9]=u2.y; vvv[10]=u2.z; vvv[11]=u2.w;
        }
        #pragma unroll
        for (int kw = 0; kw < 7; kw++) {
            #pragma unroll
            for (int o = 0; o < 4; o++) {
                int idx = o + kw + 1;
                float qbb = USEH ? qb[o][kh] : qb[o][kw];
                float t = fmaf(ql[o], kvv[idx], qbb);
                float e;
                asm("ex2.approx.f32 %0, %1;" : "=f"(e) : "f"(t));
                ssum[o] += e;
                avec[o] = fmaf(e, vvv[idx], avec[o]);
            }
        }
    }
    float inv[4];
    #pragma unroll
    for (int o = 0; o < 4; o++)
        asm("rcp.approx.f32 %0, %1;" : "=f"(inv[o]) : "f"(ssum[o]));
    float4 rr = make_float4(avec[0] * inv[0], avec[1] * inv[1],
                            avec[2] * inv[2], avec[3] * inv[3]);
    *(float4*)(orow + w0) = rr;
}

__global__ __launch_bounds__(288) void attn_kernel(
    const float* __restrict__ rel_h, const float* __restrict__ rel_w,
    float* __restrict__ out)
{
    __shared__ float kvbuf[2 * 30 * 56];
    float* ks = kvbuf;
    float* vs = kvbuf + 1680;

    int plane = blockIdx.x >> 1;
    int half  = blockIdx.x & 1;
    int y0    = half * 24;
    int ybase = y0 - 3;
    int c = plane & 255;
    bool useH = (c < 128);

    const float* kp = g_k + (size_t)plane * HW;
    const float* vp = g_v + (size_t)plane * HW;
    const float* qp = g_q + (size_t)plane * HW;
    float*       op = out + (size_t)plane * HW;

    int tid = threadIdx.x;
    int r_oob = half ? 27 : 0;   // 3 local rows with gy out of range

    // Halo clear: cols 0-3 & 52-55 of all 30 rows (120 float4) +
    // interior of the 3 OOB rows (72 float4). Disjoint from the fill region.
    if (tid < 192) {
        if (tid < 120) {
            int tile = tid / 60;
            int tt   = tid - tile * 60;
            int r    = tt >> 1;
            int side = tt & 1;
            *(float4*)(kvbuf + tile * 1680 + r * 56 + side * 52) =
                make_float4(0.f, 0.f, 0.f, 0.f);
        } else {
            int t2   = tid - 120;
            int tile = t2 / 36;
            int tt   = t2 - tile * 36;
            int rr   = r_oob + tt / 12;
            int col  = 4 + (tt % 12) * 4;
            *(float4*)(kvbuf + tile * 1680 + rr * 56 + col) =
                make_float4(0.f, 0.f, 0.f, 0.f);
        }
    }
    // Interior fill (valid rows only; writes cols 4..51)
    for (int i = tid; i < 360; i += 288) {
        int r  = i / 12;
        int x4 = (i - r * 12) << 2;
        int gy = ybase + r;
        if ((unsigned)gy < 48u) {
            *(float4*)(ks + r * 56 + x4 + 4) = *(const float4*)(kp + gy * WD + x4);
            *(float4*)(vs + r * 56 + x4 + 4) = *(const float4*)(vp + gy * WD + x4);
        }
    }
    const float* rb = useH ? (rel_h + c * 7) : (rel_w + (c - 128) * 7);
    float bias[7];
    #pragma unroll
    for (int j = 0; j < 7; j++) bias[j] = rb[j];
    __syncthreads();

    int r  = tid / 12;
    int w0 = (tid - r * 12) << 2;
    int gy = y0 + r;
    const float* qrow = qp + gy * WD;
    float*       orow = op + gy * WD;

    if (useH) attn_body<true >(ks, vs, qrow, orow, bias, r, w0);
    else      attn_body<false>(ks, vs, qrow, orow, bias, r, w0);
}

extern "C" void kernel_launch(void* const* d_in, const int* in_sizes, int n_in,
                              void* d_out, int out_size) {
    const float* x  = (const float*)d_in[0];
    const float* wq = (const float*)d_in[1];
    const float* wk = (const float*)d_in[2];
    const float* wv = (const float*)d_in[3];
    const float* rh = (const float*)d_in[4];
    const float* rw = (const float*)d_in[5];

    cudaFuncSetAttribute(gemm_kernel, cudaFuncAttributeMaxDynamicSharedMemorySize,
                         GEMM_SMEM);

    prep_kernel<<<dim3(18, 8, 3), 256>>>(x, wq, wk, wv);
    gemm_kernel<<<dim3(36, 12), 256, GEMM_SMEM>>>();
    attn_kernel<<<1024, 288>>>(rh, rw, (float*)d_out);
}